// round 1
// baseline (speedup 1.0000x reference)
#include <cuda_runtime.h>
#include <cuda_bf16.h>

// FAVOR+ linear attention, fp32 SIMT tile kernels.
// B=8, Q=K=8192, D=DV=m=128 (dims derived from in_sizes where possible).
//
// Pipeline:
//   init_kernel : zero g_kv/g_ksum scratch
//   kv_kernel   : ks' = phi(ks*c) masked; g_kv += ks'^T @ vs; g_ksum += sum ks'
//   out_kernel  : qs' = phi(qs*c); out = (qs' @ g_kv) / max(qs'.g_ksum, EPS)

#define TILE 128
#define LD   132                 // smem leading dim (floats), 16B-aligned, conflict-tamed
#define ROWF (128 * LD)          // floats per 128x128 padded tile

static constexpr float NORMALIZER = 0.29730177875068026f;  // 128^-0.25
static constexpr float RSQRT_M    = 0.08838834764831845f;  // 1/sqrt(128)
static constexpr float EPS_DEN    = 1e-6f;

#define MAX_B 8
__device__ float g_kv[MAX_B * 128 * 128];
__device__ float g_ksum[MAX_B * 128];

// ---------------------------------------------------------------------------
// valid_lens may arrive as int32 (JAX x64-off canonicalization) or int64.
// Detect: int64 little-endian => odd 32-bit words are 0 and even words in range.
// All detection reads are within the first 32 bytes (safe for both layouts).
// ---------------------------------------------------------------------------
__device__ __forceinline__ int get_vl(const void* p, int b, int K) {
    const int* pi = (const int*)p;
    bool is64 = (pi[1] == 0) && (pi[3] == 0) && (pi[5] == 0) && (pi[7] == 0) &&
                (pi[0] >= 0 && pi[0] <= K) && (pi[2] >= 0 && pi[2] <= K) &&
                (pi[4] >= 0 && pi[4] <= K) && (pi[6] >= 0 && pi[6] <= K);
    return is64 ? pi[2 * b] : pi[b];
}

// ---------------------------------------------------------------------------
// Load a 128x128 fp32 tile (row-major, row stride 128) into smem TRANSPOSED:
// s[d*LD + row] = g[row*128 + d] * scale.  256 threads.
// Lane map: 8 rows x 4 float4 per warp-iter -> full 32B-sector efficiency on
// global reads, <=2-way conflicts on the scattered STS.
// ---------------------------------------------------------------------------
__device__ __forceinline__ void load_tile_T(const float* __restrict__ g,
                                            float* __restrict__ s, float scale) {
    int lane = threadIdx.x & 31;
    int warp = threadIdx.x >> 5;      // 0..7
    int row0 = lane >> 2;             // 0..7
    int d4l  = lane & 3;              // 0..3
#pragma unroll
    for (int t = 0; t < 16; t++) {
        int tt  = t * 8 + warp;       // 0..127
        int rg  = tt & 15;            // row group 0..15
        int dg  = tt >> 4;            // d4 group 0..7
        int row = rg * 8 + row0;
        int d4  = dg * 4 + d4l;
        float4 v = *(const float4*)(g + row * 128 + d4 * 4);
        s[(d4 * 4 + 0) * LD + row] = v.x * scale;
        s[(d4 * 4 + 1) * LD + row] = v.y * scale;
        s[(d4 * 4 + 2) * LD + row] = v.z * scale;
        s[(d4 * 4 + 3) * LD + row] = v.w * scale;
    }
}

// Row-major copy of a 128x128 fp32 tile into padded smem (for V / KV tiles).
__device__ __forceinline__ void load_tile_RM(const float* __restrict__ g,
                                             float* __restrict__ s) {
    int tid = threadIdx.x;
#pragma unroll
    for (int t = 0; t < 16; t++) {
        int idx = t * 256 + tid;      // 0..4095 float4 slots
        int row = idx >> 5;
        int d4  = idx & 31;
        float4 v = *(const float4*)(g + row * 128 + d4 * 4);
        *(float4*)(s + row * LD + d4 * 4) = v;
    }
}

// ---------------------------------------------------------------------------
// 128x128x128 register-tiled GEMM, both operands k-major in smem:
// acc[r][c] += sum_d A[d*LD + i0+r] * B[d*LD + j0+c]
// Thread grid 16x16, 8x8 fragments. a-reads: 2 float4 (2 addrs/warp,
// broadcast); b-reads: 2 float4 (4-phase inherent). FFMA-issue-bound.
// ---------------------------------------------------------------------------
__device__ __forceinline__ void gemm128(const float* __restrict__ A,
                                        const float* __restrict__ B,
                                        float acc[8][8], int i0, int j0) {
#pragma unroll 4
    for (int d = 0; d < 128; d++) {
        float4 a0 = *(const float4*)(A + d * LD + i0);
        float4 a1 = *(const float4*)(A + d * LD + i0 + 4);
        float4 b0 = *(const float4*)(B + d * LD + j0);
        float4 b1 = *(const float4*)(B + d * LD + j0 + 4);
        float av[8] = {a0.x, a0.y, a0.z, a0.w, a1.x, a1.y, a1.z, a1.w};
        float bv[8] = {b0.x, b0.y, b0.z, b0.w, b1.x, b1.y, b1.z, b1.w};
#pragma unroll
        for (int r = 0; r < 8; r++)
#pragma unroll
            for (int c = 0; c < 8; c++)
                acc[r][c] += av[r] * bv[c];
    }
}

// ---------------------------------------------------------------------------
__global__ void init_kernel(int b_count) {
    int i = blockIdx.x * blockDim.x + threadIdx.x;
    int n_kv = b_count * 128 * 128;
    if (i < n_kv) g_kv[i] = 0.0f;
    if (i < b_count * 128) g_ksum[i] = 0.0f;
}

// ---------------------------------------------------------------------------
// kv_kernel: grid (K/128, B), 256 threads.
// ---------------------------------------------------------------------------
__global__ void __launch_bounds__(256, 1)
kv_kernel(const float* __restrict__ ks, const float* __restrict__ vs,
          const float* __restrict__ proj, const void* __restrict__ vl,
          int K) {
    extern __shared__ float sm[];
    float* projT = sm;                 // [d][m]  (proj transposed)
    float* XT    = sm + ROWF;          // [d][k]  then reused as V [k][v]
    float* S     = sm + 2 * ROWF;      // [k][m]
    float* hbuf  = sm + 3 * ROWF;      // [128]

    int b  = blockIdx.y;
    int k0 = blockIdx.x * TILE;
    int tid = threadIdx.x;
    int tx = tid & 15, ty = tid >> 4;

    const float* ks_tile = ks + ((long)b * K + k0) * 128;
    const float* vs_tile = vs + ((long)b * K + k0) * 128;

    load_tile_T(proj, projT, 1.0f);
    load_tile_T(ks_tile, XT, NORMALIZER);
    __syncthreads();

    // h[i] = 0.5 * ||x_i||^2 (scaled x). Column reads: lanes hit consecutive
    // banks -> conflict-free.
    if (tid < 128) {
        float h = 0.0f;
#pragma unroll 8
        for (int d = 0; d < 128; d++) {
            float x = XT[d * LD + tid];
            h += x * x;
        }
        hbuf[tid] = 0.5f * h;
    }
    __syncthreads();

    // P = Xc @ proj^T  (output [k][m])
    float p[8][8];
#pragma unroll
    for (int r = 0; r < 8; r++)
#pragma unroll
        for (int c = 0; c < 8; c++) p[r][c] = 0.0f;
    gemm128(XT, projT, p, ty * 8, tx * 8);

    int vlb = get_vl(vl, b, K);

    // S = exp(P - h) * rsqrt(m), masked rows zeroed. float4 row-major writes.
#pragma unroll
    for (int r = 0; r < 8; r++) {
        int krow = ty * 8 + r;
        float hr = hbuf[krow];
        float rowscale = ((k0 + krow) < vlb) ? RSQRT_M : 0.0f;
        float4 o0, o1;
        o0.x = __expf(p[r][0] - hr) * rowscale;
        o0.y = __expf(p[r][1] - hr) * rowscale;
        o0.z = __expf(p[r][2] - hr) * rowscale;
        o0.w = __expf(p[r][3] - hr) * rowscale;
        o1.x = __expf(p[r][4] - hr) * rowscale;
        o1.y = __expf(p[r][5] - hr) * rowscale;
        o1.z = __expf(p[r][6] - hr) * rowscale;
        o1.w = __expf(p[r][7] - hr) * rowscale;
        *(float4*)(S + krow * LD + tx * 8)     = o0;
        *(float4*)(S + krow * LD + tx * 8 + 4) = o1;
    }
    __syncthreads();   // S ready; XT (ks) reads complete

    // V tile into XT buffer; ksum column-sums of S in parallel.
    load_tile_RM(vs_tile, XT);
    if (tid < 128) {
        float ssum = 0.0f;
#pragma unroll 8
        for (int k = 0; k < 128; k++) ssum += S[k * LD + tid];
        atomicAdd(&g_ksum[b * 128 + tid], ssum);
    }
    __syncthreads();

    // kv[m][v] += sum_k S[k][m] * V[k][v]
    float acc[8][8];
#pragma unroll
    for (int r = 0; r < 8; r++)
#pragma unroll
        for (int c = 0; c < 8; c++) acc[r][c] = 0.0f;
    gemm128(S, XT, acc, ty * 8, tx * 8);

    float* kvb = g_kv + b * 128 * 128;
#pragma unroll
    for (int r = 0; r < 8; r++)
#pragma unroll
        for (int c = 0; c < 8; c++)
            atomicAdd(&kvb[(ty * 8 + r) * 128 + tx * 8 + c], acc[r][c]);
}

// ---------------------------------------------------------------------------
// out_kernel: grid (Q/128, B), 256 threads.
// Computes S^T directly (operand swap) so no conflicted transpose store.
// ---------------------------------------------------------------------------
__global__ void __launch_bounds__(256, 1)
out_kernel(const float* __restrict__ qs, const float* __restrict__ proj,
           float* __restrict__ out, int Q) {
    extern __shared__ float sm[];
    float* projT  = sm;                 // [d][m], reused as KV [m][v]
    float* XT     = sm + ROWF;          // [d][q]
    float* ST     = sm + 2 * ROWF;      // [m][q]
    float* hbuf   = sm + 3 * ROWF;      // [128] per-q h
    float* denb   = sm + 3 * ROWF + 128;
    float* ksum_s = sm + 3 * ROWF + 256;

    int b  = blockIdx.y;
    int q0 = blockIdx.x * TILE;
    int tid = threadIdx.x;
    int tx = tid & 15, ty = tid >> 4;

    load_tile_T(proj, projT, 1.0f);
    load_tile_T(qs + ((long)b * Q + q0) * 128, XT, NORMALIZER);
    if (tid < 128) ksum_s[tid] = g_ksum[b * 128 + tid];
    __syncthreads();

    if (tid < 128) {
        float h = 0.0f;
#pragma unroll 8
        for (int d = 0; d < 128; d++) {
            float x = XT[d * LD + tid];
            h += x * x;
        }
        hbuf[tid] = 0.5f * h;
    }
    __syncthreads();

    // P^T[m][q] = sum_d projT[d][m] * XT[d][q]
    float p[8][8];
#pragma unroll
    for (int r = 0; r < 8; r++)
#pragma unroll
        for (int c = 0; c < 8; c++) p[r][c] = 0.0f;
    gemm128(projT, XT, p, ty * 8, tx * 8);

    // ST[m][q] = exp(P^T - h[q]) * rsqrt(m)
#pragma unroll
    for (int r = 0; r < 8; r++) {
        int mrow = ty * 8 + r;
        float4 o0, o1;
        o0.x = __expf(p[r][0] - hbuf[tx * 8 + 0]) * RSQRT_M;
        o0.y = __expf(p[r][1] - hbuf[tx * 8 + 1]) * RSQRT_M;
        o0.z = __expf(p[r][2] - hbuf[tx * 8 + 2]) * RSQRT_M;
        o0.w = __expf(p[r][3] - hbuf[tx * 8 + 3]) * RSQRT_M;
        o1.x = __expf(p[r][4] - hbuf[tx * 8 + 4]) * RSQRT_M;
        o1.y = __expf(p[r][5] - hbuf[tx * 8 + 5]) * RSQRT_M;
        o1.z = __expf(p[r][6] - hbuf[tx * 8 + 6]) * RSQRT_M;
        o1.w = __expf(p[r][7] - hbuf[tx * 8 + 7]) * RSQRT_M;
        *(float4*)(ST + mrow * LD + tx * 8)     = o0;
        *(float4*)(ST + mrow * LD + tx * 8 + 4) = o1;
    }
    __syncthreads();   // ST ready; projT reads complete

    // KV tile into projT buffer; den[q] = sum_m ST[m][q]*ksum[m] in parallel.
    load_tile_RM(g_kv + b * 128 * 128, projT);
    if (tid < 128) {
        float dn = 0.0f;
#pragma unroll 8
        for (int m = 0; m < 128; m++) dn += ST[m * LD + tid] * ksum_s[m];
        denb[tid] = (dn < EPS_DEN) ? EPS_DEN : dn;
    }
    __syncthreads();

    // out[q][v] = sum_m ST[m][q] * KV[m][v] / den[q]
    float acc[8][8];
#pragma unroll
    for (int r = 0; r < 8; r++)
#pragma unroll
        for (int c = 0; c < 8; c++) acc[r][c] = 0.0f;
    gemm128(ST, projT, acc, ty * 8, tx * 8);

#pragma unroll
    for (int r = 0; r < 8; r++) {
        int q = q0 + ty * 8 + r;
        float inv = 1.0f / denb[ty * 8 + r];
        float4 o0, o1;
        o0.x = acc[r][0] * inv; o0.y = acc[r][1] * inv;
        o0.z = acc[r][2] * inv; o0.w = acc[r][3] * inv;
        o1.x = acc[r][4] * inv; o1.y = acc[r][5] * inv;
        o1.z = acc[r][6] * inv; o1.w = acc[r][7] * inv;
        float* orow = out + ((long)b * Q + q) * 128 + tx * 8;
        *(float4*)(orow)     = o0;
        *(float4*)(orow + 4) = o1;
    }
}

// ---------------------------------------------------------------------------
extern "C" void kernel_launch(void* const* d_in, const int* in_sizes, int n_in,
                              void* d_out, int out_size) {
    const float* qs   = (const float*)d_in[0];
    const float* ks   = (const float*)d_in[1];
    const float* vs   = (const float*)d_in[2];
    const float* proj = (const float*)d_in[3];
    const void*  vl   = d_in[4];

    int B = in_sizes[4];
    if (B > MAX_B) B = MAX_B;
    int Q = in_sizes[0] / (B * 128);
    int K = in_sizes[1] / (B * 128);

    const int smem_bytes = (3 * ROWF + 512) * (int)sizeof(float);  // 204800 B
    cudaFuncSetAttribute(kv_kernel,  cudaFuncAttributeMaxDynamicSharedMemorySize, smem_bytes);
    cudaFuncSetAttribute(out_kernel, cudaFuncAttributeMaxDynamicSharedMemorySize, smem_bytes);

    int n_init = B * 128 * 128;
    init_kernel<<<(n_init + 255) / 256, 256>>>(B);

    dim3 grid_kv(K / TILE, B);
    kv_kernel<<<grid_kv, 256, smem_bytes>>>(ks, vs, proj, vl, K);

    dim3 grid_out(Q / TILE, B);
    out_kernel<<<grid_out, 256, smem_bytes>>>(qs, proj, (float*)d_out, Q);
}